// round 11
// baseline (speedup 1.0000x reference)
#include <cuda_runtime.h>
#include <cstdint>

typedef uint32_t u32;

__device__ __forceinline__ u32 pkbf(float lo, float hi) {
    u32 r; asm("cvt.rn.bf16x2.f32 %0, %1, %2;" : "=r"(r) : "f"(hi), "f"(lo)); return r;
}
__device__ __forceinline__ float bflo(u32 h) { return __uint_as_float(h << 16); }
__device__ __forceinline__ float bfhi(u32 h) { return __uint_as_float(h & 0xFFFF0000u); }
__device__ __forceinline__ void split2(float a, float b, u32& hp, u32& lp) {
    hp = pkbf(a, b);
    lp = pkbf(a - bflo(hp), b - bfhi(hp));
}

#define MMA(d, a0, a1, a2, a3, b0, b1)                                      \
    asm volatile("mma.sync.aligned.m16n8k16.row.col.f32.bf16.bf16.f32 "     \
                 "{%0,%1,%2,%3},{%4,%5,%6,%7},{%8,%9},{%0,%1,%2,%3};"       \
                 : "+f"((d)[0]), "+f"((d)[1]), "+f"((d)[2]), "+f"((d)[3])   \
                 : "r"(a0), "r"(a1), "r"(a2), "r"(a3), "r"(b0), "r"(b1))

// Per-lane weight fragments: uint4 = {hi_b0, hi_b1, lo_b0, lo_b1}
struct __align__(16) WBlob {
    uint4 w1[4][4][32];   // GEMM1, K-permuted for coalesced x loads
    uint4 w2[2][4][32];   // GEMM2, identity layout
    uint4 w3[2][8][32];   // GEMM3, N-permuted so store j of lane t is float4 @ col 16j+4t
    float ab[32], cb[32], bo[64];
    float l1g[32], l1b[32], l2g[32], l2b[32];
};
__device__ WBlob g_wp;

// ---------------- prep (layouts unchanged) ----------------
__global__ void prep_kernel(
    const float* __restrict__ w1,  const float* __restrict__ b1,
    const float* __restrict__ wv1, const float* __restrict__ bv1, const float* __restrict__ g1,
    const float* __restrict__ l1g, const float* __restrict__ l1b,
    const float* __restrict__ w2,  const float* __restrict__ b2,
    const float* __restrict__ wv2, const float* __restrict__ bv2, const float* __restrict__ g2,
    const float* __restrict__ l2g, const float* __restrict__ l2b,
    const float* __restrict__ wo,  const float* __restrict__ bo)
{
    __shared__ float Af[64 * 32];
    __shared__ float Cf[32 * 32];
    const int t = threadIdx.x;
    const float g1v = g1[0], g2v = g2[0];

    for (int idx = t; idx < 64 * 32; idx += blockDim.x) {
        int i = idx >> 5, j = idx & 31;
        float s = 0.f;
        for (int m = 0; m < 32; m++) s += w1[i * 32 + m] * wv1[m * 32 + j];
        Af[idx] = w1[i * 32 + j] + g1v * s;
    }
    for (int idx = t; idx < 32 * 32; idx += blockDim.x) {
        int i = idx >> 5, j = idx & 31;
        float s = 0.f;
        for (int m = 0; m < 32; m++) s += w2[i * 32 + m] * wv2[m * 32 + j];
        Cf[idx] = w2[i * 32 + j] + g2v * s;
    }
    __syncthreads();

    for (int idx = t; idx < 4 * 4 * 32; idx += blockDim.x) {
        int kk = idx >> 7, nn = (idx >> 5) & 3, ln = idx & 31;
        int gg = ln >> 2, tt = ln & 3;
        int kb = 16 * kk + 4 * tt, n = 8 * nn + gg;
        float a0 = Af[kb * 32 + n],       a1 = Af[(kb + 1) * 32 + n];
        float a2 = Af[(kb + 2) * 32 + n], a3 = Af[(kb + 3) * 32 + n];
        uint4 v;
        v.x = pkbf(a0, a1); v.y = pkbf(a2, a3);
        v.z = pkbf(a0 - bflo(v.x), a1 - bfhi(v.x));
        v.w = pkbf(a2 - bflo(v.y), a3 - bfhi(v.y));
        g_wp.w1[kk][nn][ln] = v;
    }
    for (int idx = t; idx < 2 * 4 * 32; idx += blockDim.x) {
        int kk = idx >> 7, nn = (idx >> 5) & 3, ln = idx & 31;
        int gg = ln >> 2, tt = ln & 3;
        int k0 = 16 * kk + 2 * tt, n = 8 * nn + gg;
        float a0 = Cf[k0 * 32 + n],       a1 = Cf[(k0 + 1) * 32 + n];
        float a2 = Cf[(k0 + 8) * 32 + n], a3 = Cf[(k0 + 9) * 32 + n];
        uint4 v;
        v.x = pkbf(a0, a1); v.y = pkbf(a2, a3);
        v.z = pkbf(a0 - bflo(v.x), a1 - bfhi(v.x));
        v.w = pkbf(a2 - bflo(v.y), a3 - bfhi(v.y));
        g_wp.w2[kk][nn][ln] = v;
    }
    for (int idx = t; idx < 2 * 8 * 32; idx += blockDim.x) {
        int kk = idx >> 8, nn = (idx >> 5) & 7, ln = idx & 31;
        int gg = ln >> 2, tt = ln & 3;
        int k0 = 16 * kk + 2 * tt;
        int c = 16 * (nn >> 1) + 4 * (gg >> 1) + 2 * (nn & 1) + (gg & 1);
        float a0 = wo[k0 * 64 + c],       a1 = wo[(k0 + 1) * 64 + c];
        float a2 = wo[(k0 + 8) * 64 + c], a3 = wo[(k0 + 9) * 64 + c];
        uint4 v;
        v.x = pkbf(a0, a1); v.y = pkbf(a2, a3);
        v.z = pkbf(a0 - bflo(v.x), a1 - bfhi(v.x));
        v.w = pkbf(a2 - bflo(v.y), a3 - bfhi(v.y));
        g_wp.w3[kk][nn][ln] = v;
    }
    if (t < 32) {
        int j = t;
        float s1 = 0.f, s2 = 0.f;
        for (int m = 0; m < 32; m++) {
            s1 += b1[m] * wv1[m * 32 + j];
            s2 += b2[m] * wv2[m * 32 + j];
        }
        g_wp.ab[j] = b1[j] + g1v * (s1 + bv1[j]);
        g_wp.cb[j] = b2[j] + g2v * (s2 + bv2[j]);
        g_wp.l1g[j] = l1g[j]; g_wp.l1b[j] = l1b[j];
        g_wp.l2g[j] = l2g[j]; g_wp.l2b[j] = l2b[j];
    }
    if (t < 64) g_wp.bo[t] = bo[t];
}

// bias + LN + leaky on [16 x 32] block; emit next-stage A frags
__device__ __forceinline__ void ln_block(float acc[4][4],
                                         const float* __restrict__ bias,
                                         const float* __restrict__ gg,
                                         const float* __restrict__ bb,
                                         int t, u32 oh[2][4], u32 ol[2][4])
{
    float s0 = 0.f, q0 = 0.f, s1 = 0.f, q1 = 0.f;
#pragma unroll
    for (int nn = 0; nn < 4; nn++) {
        float2 bv = *(const float2*)(bias + 8 * nn + 2 * t);
        acc[nn][0] += bv.x; acc[nn][1] += bv.y;
        acc[nn][2] += bv.x; acc[nn][3] += bv.y;
        s0 += acc[nn][0] + acc[nn][1];
        q0 += acc[nn][0] * acc[nn][0] + acc[nn][1] * acc[nn][1];
        s1 += acc[nn][2] + acc[nn][3];
        q1 += acc[nn][2] * acc[nn][2] + acc[nn][3] * acc[nn][3];
    }
#pragma unroll
    for (int m = 1; m < 4; m <<= 1) {
        s0 += __shfl_xor_sync(0xffffffffu, s0, m, 4);
        q0 += __shfl_xor_sync(0xffffffffu, q0, m, 4);
        s1 += __shfl_xor_sync(0xffffffffu, s1, m, 4);
        q1 += __shfl_xor_sync(0xffffffffu, q1, m, 4);
    }
    const float c = 1.0f / 32.0f;
    const float m0 = s0 * c, r0 = rsqrtf(fmaf(-m0, m0, q0 * c) + 1e-5f);
    const float m1 = s1 * c, r1 = rsqrtf(fmaf(-m1, m1, q1 * c) + 1e-5f);

    float y[4][4];
#pragma unroll
    for (int nn = 0; nn < 4; nn++) {
        float2 gv = *(const float2*)(gg + 8 * nn + 2 * t);
        float2 bv = *(const float2*)(bb + 8 * nn + 2 * t);
        float u;
        u = fmaf((acc[nn][0] - m0) * r0, gv.x, bv.x); y[nn][0] = fmaxf(u, 0.01f * u);
        u = fmaf((acc[nn][1] - m0) * r0, gv.y, bv.y); y[nn][1] = fmaxf(u, 0.01f * u);
        u = fmaf((acc[nn][2] - m1) * r1, gv.x, bv.x); y[nn][2] = fmaxf(u, 0.01f * u);
        u = fmaf((acc[nn][3] - m1) * r1, gv.y, bv.y); y[nn][3] = fmaxf(u, 0.01f * u);
    }
#pragma unroll
    for (int kk = 0; kk < 2; kk++) {
        split2(y[2 * kk][0],     y[2 * kk][1],     oh[kk][0], ol[kk][0]);
        split2(y[2 * kk][2],     y[2 * kk][3],     oh[kk][1], ol[kk][1]);
        split2(y[2 * kk + 1][0], y[2 * kk + 1][1], oh[kk][2], ol[kk][2]);
        split2(y[2 * kk + 1][2], y[2 * kk + 1][3], oh[kk][3], ol[kk][3]);
    }
}

// load x for a 32-row pair: row groups base+g, +8, +16, +24
__device__ __forceinline__ void loadx32(const float* __restrict__ x, int pair, int g, int t,
                                        int nrows, float4 xr[4][4])
{
#pragma unroll
    for (int rg = 0; rg < 4; rg++) {
        const int r = pair * 32 + 8 * rg + g;
        const float* b = x + (size_t)r * 64 + 4 * t;
        const bool v = r < nrows;
#pragma unroll
        for (int kk = 0; kk < 4; kk++)
            xr[rg][kk] = v ? __ldcs((const float4*)(b + 16 * kk)) : make_float4(0.f, 0.f, 0.f, 0.f);
    }
}

// ---------------- fused kernel: 1 warp per 32-row pair, 3 CTAs/SM ----------------
__global__ void __launch_bounds__(128, 3)
fused_kernel(const float* __restrict__ x, float* __restrict__ out, int nrows, int npairs)
{
    __shared__ uint4 w1s[512];
    __shared__ uint4 w2s[256];
    __shared__ uint4 w3s[512];
    __shared__ float sp[192];
    __shared__ float bos[64];
    const int tid = threadIdx.x;
    {
        const uint4* s1 = (const uint4*)g_wp.w1;
        const uint4* s2 = (const uint4*)g_wp.w2;
        const uint4* s3 = (const uint4*)g_wp.w3;
        for (int i = tid; i < 512; i += 128) { w1s[i] = s1[i]; w3s[i] = s3[i]; }
        for (int i = tid; i < 256; i += 128) w2s[i] = s2[i];
        if (tid < 32) {
            sp[tid]       = g_wp.ab[tid];
            sp[32 + tid]  = g_wp.l1g[tid];
            sp[64 + tid]  = g_wp.l1b[tid];
            sp[96 + tid]  = g_wp.cb[tid];
            sp[128 + tid] = g_wp.l2g[tid];
            sp[160 + tid] = g_wp.l2b[tid];
        }
        if (tid < 64) bos[tid] = g_wp.bo[tid];
    }
    const int wid = tid >> 5, lane = tid & 31;
    const int g = lane >> 2, t = lane & 3;
    __syncthreads();

    const int stride = gridDim.x * 4;
    int pair = blockIdx.x * 4 + wid;
    if (pair >= npairs) return;

    float4 xr[4][4];                       // [row-group][kk]
    loadx32(x, pair, g, t, nrows, xr);

    for (; pair < npairs; pair += stride) {
        // ---- GEMM1 both tiles, frags built per-kk (weight LDS feeds 6 MMAs) ----
        float accA[4][4], accB[4][4];
#pragma unroll
        for (int nn = 0; nn < 4; nn++) {
            accA[nn][0] = accA[nn][1] = accA[nn][2] = accA[nn][3] = 0.f;
            accB[nn][0] = accB[nn][1] = accB[nn][2] = accB[nn][3] = 0.f;
        }
#pragma unroll
        for (int kk = 0; kk < 4; kk++) {
            u32 hA[4], lA[4], hB[4], lB[4];
            split2(xr[0][kk].x, xr[0][kk].y, hA[0], lA[0]);
            split2(xr[1][kk].x, xr[1][kk].y, hA[1], lA[1]);
            split2(xr[0][kk].z, xr[0][kk].w, hA[2], lA[2]);
            split2(xr[1][kk].z, xr[1][kk].w, hA[3], lA[3]);
            split2(xr[2][kk].x, xr[2][kk].y, hB[0], lB[0]);
            split2(xr[3][kk].x, xr[3][kk].y, hB[1], lB[1]);
            split2(xr[2][kk].z, xr[2][kk].w, hB[2], lB[2]);
            split2(xr[3][kk].z, xr[3][kk].w, hB[3], lB[3]);
#pragma unroll
            for (int nn = 0; nn < 4; nn++) {
                uint4 w = w1s[(kk * 4 + nn) * 32 + lane];
                MMA(accA[nn], hA[0], hA[1], hA[2], hA[3], w.x, w.y);
                MMA(accA[nn], lA[0], lA[1], lA[2], lA[3], w.x, w.y);
                MMA(accA[nn], hA[0], hA[1], hA[2], hA[3], w.z, w.w);
                MMA(accB[nn], hB[0], hB[1], hB[2], hB[3], w.x, w.y);
                MMA(accB[nn], lB[0], lB[1], lB[2], lB[3], w.x, w.y);
                MMA(accB[nn], hB[0], hB[1], hB[2], hB[3], w.z, w.w);
            }
        }

        // ---- register prefetch of next pair (xr dead now) ----
        if (pair + stride < npairs) loadx32(x, pair + stride, g, t, nrows, xr);

        // ---- LN1 + GEMM2 (w2 from smem) + LN2 ----
        u32 a2hA[2][4], a2lA[2][4], a2hB[2][4], a2lB[2][4];
        ln_block(accA, sp + 0, sp + 32, sp + 64, t, a2hA, a2lA);
        ln_block(accB, sp + 0, sp + 32, sp + 64, t, a2hB, a2lB);

        float c2A[4][4], c2B[4][4];
#pragma unroll
        for (int nn = 0; nn < 4; nn++) {
            c2A[nn][0] = c2A[nn][1] = c2A[nn][2] = c2A[nn][3] = 0.f;
            c2B[nn][0] = c2B[nn][1] = c2B[nn][2] = c2B[nn][3] = 0.f;
#pragma unroll
            for (int kk = 0; kk < 2; kk++) {
                uint4 w = w2s[(kk * 4 + nn) * 32 + lane];
                MMA(c2A[nn], a2hA[kk][0], a2hA[kk][1], a2hA[kk][2], a2hA[kk][3], w.x, w.y);
                MMA(c2A[nn], a2lA[kk][0], a2lA[kk][1], a2lA[kk][2], a2lA[kk][3], w.x, w.y);
                MMA(c2A[nn], a2hA[kk][0], a2hA[kk][1], a2hA[kk][2], a2hA[kk][3], w.z, w.w);
                MMA(c2B[nn], a2hB[kk][0], a2hB[kk][1], a2hB[kk][2], a2hB[kk][3], w.x, w.y);
                MMA(c2B[nn], a2lB[kk][0], a2lB[kk][1], a2lB[kk][2], a2lB[kk][3], w.x, w.y);
                MMA(c2B[nn], a2hB[kk][0], a2hB[kk][1], a2hB[kk][2], a2hB[kk][3], w.z, w.w);
            }
        }

        u32 a3hA[2][4], a3lA[2][4], a3hB[2][4], a3lB[2][4];
        ln_block(c2A, sp + 96, sp + 128, sp + 160, t, a3hA, a3lA);
        ln_block(c2B, sp + 96, sp + 128, sp + 160, t, a3hB, a3lB);

        const int base = pair * 32 + g;

        // ---- GEMM3 tile A (staged: compute, store, release regs) ----
        {
            float o3[8][4];
#pragma unroll
            for (int nn = 0; nn < 8; nn++) {
                o3[nn][0] = o3[nn][1] = o3[nn][2] = o3[nn][3] = 0.f;
#pragma unroll
                for (int kk = 0; kk < 2; kk++) {
                    uint4 w = w3s[(kk * 8 + nn) * 32 + lane];
                    MMA(o3[nn], a3hA[kk][0], a3hA[kk][1], a3hA[kk][2], a3hA[kk][3], w.x, w.y);
                    MMA(o3[nn], a3lA[kk][0], a3lA[kk][1], a3lA[kk][2], a3lA[kk][3], w.x, w.y);
                    MMA(o3[nn], a3hA[kk][0], a3hA[kk][1], a3hA[kk][2], a3hA[kk][3], w.z, w.w);
                }
            }
            const int r0 = base, r1 = base + 8;
            const bool v0 = r0 < nrows, v1 = r1 < nrows;
#pragma unroll
            for (int j = 0; j < 4; j++) {
                float4 b = *(const float4*)(bos + 16 * j + 4 * t);
                if (v0) {
                    float4 v;
                    v.x = o3[2 * j][0]     + b.x;
                    v.y = o3[2 * j][1]     + b.y;
                    v.z = o3[2 * j + 1][0] + b.z;
                    v.w = o3[2 * j + 1][1] + b.w;
                    __stcs((float4*)(out + (size_t)r0 * 64 + 16 * j + 4 * t), v);
                }
                if (v1) {
                    float4 v;
                    v.x = o3[2 * j][2]     + b.x;
                    v.y = o3[2 * j][3]     + b.y;
                    v.z = o3[2 * j + 1][2] + b.z;
                    v.w = o3[2 * j + 1][3] + b.w;
                    __stcs((float4*)(out + (size_t)r1 * 64 + 16 * j + 4 * t), v);
                }
            }
        }

        // ---- GEMM3 tile B ----
        {
            float o3[8][4];
#pragma unroll
            for (int nn = 0; nn < 8; nn++) {
                o3[nn][0] = o3[nn][1] = o3[nn][2] = o3[nn][3] = 0.f;
#pragma unroll
                for (int kk = 0; kk < 2; kk++) {
                    uint4 w = w3s[(kk * 8 + nn) * 32 + lane];
                    MMA(o3[nn], a3hB[kk][0], a3hB[kk][1], a3hB[kk][2], a3hB[kk][3], w.x, w.y);
                    MMA(o3[nn], a3lB[kk][0], a3lB[kk][1], a3lB[kk][2], a3lB[kk][3], w.x, w.y);
                    MMA(o3[nn], a3hB[kk][0], a3hB[kk][1], a3hB[kk][2], a3hB[kk][3], w.z, w.w);
                }
            }
            const int r0 = base + 16, r1 = base + 24;
            const bool v0 = r0 < nrows, v1 = r1 < nrows;
#pragma unroll
            for (int j = 0; j < 4; j++) {
                float4 b = *(const float4*)(bos + 16 * j + 4 * t);
                if (v0) {
                    float4 v;
                    v.x = o3[2 * j][0]     + b.x;
                    v.y = o3[2 * j][1]     + b.y;
                    v.z = o3[2 * j + 1][0] + b.z;
                    v.w = o3[2 * j + 1][1] + b.w;
                    __stcs((float4*)(out + (size_t)r0 * 64 + 16 * j + 4 * t), v);
                }
                if (v1) {
                    float4 v;
                    v.x = o3[2 * j][2]     + b.x;
                    v.y = o3[2 * j][3]     + b.y;
                    v.z = o3[2 * j + 1][2] + b.z;
                    v.w = o3[2 * j + 1][3] + b.w;
                    __stcs((float4*)(out + (size_t)r1 * 64 + 16 * j + 4 * t), v);
                }
            }
        }
    }
}

extern "C" void kernel_launch(void* const* d_in, const int* in_sizes, int n_in,
                              void* d_out, int out_size)
{
    const float* x   = (const float*)d_in[0];
    const float* w1  = (const float*)d_in[1];
    const float* b1  = (const float*)d_in[2];
    const float* wv1 = (const float*)d_in[7];
    const float* bv1 = (const float*)d_in[8];
    const float* g1  = (const float*)d_in[9];
    const float* l1g = (const float*)d_in[10];
    const float* l1b = (const float*)d_in[11];
    const float* w2  = (const float*)d_in[12];
    const float* b2  = (const float*)d_in[13];
    const float* wv2 = (const float*)d_in[18];
    const float* bv2 = (const float*)d_in[19];
    const float* g2  = (const float*)d_in[20];
    const float* l2g = (const float*)d_in[21];
    const float* l2b = (const float*)d_in[22];
    const float* wo  = (const float*)d_in[23];
    const float* bo  = (const float*)d_in[24];

    const int B = in_sizes[0] / 64;
    const int npairs = (B + 31) / 32;

    prep_kernel<<<1, 256>>>(w1, b1, wv1, bv1, g1, l1g, l1b,
                            w2, b2, wv2, bv2, g2, l2g, l2b, wo, bo);

    int grid = 3 * 148;                       // 3 CTAs/SM x 4 warps, persistent
    int need = (npairs + 3) / 4;
    if (grid > need) grid = need;
    fused_kernel<<<grid, 128>>>(x, (float*)d_out, B, npairs);
}

// round 12
// speedup vs baseline: 1.1223x; 1.1223x over previous
#include <cuda_runtime.h>
#include <cstdint>

typedef uint32_t u32;

__device__ __forceinline__ u32 pkbf(float lo, float hi) {
    u32 r; asm("cvt.rn.bf16x2.f32 %0, %1, %2;" : "=r"(r) : "f"(hi), "f"(lo)); return r;
}
__device__ __forceinline__ float bflo(u32 h) { return __uint_as_float(h << 16); }
__device__ __forceinline__ float bfhi(u32 h) { return __uint_as_float(h & 0xFFFF0000u); }
__device__ __forceinline__ void split2(float a, float b, u32& hp, u32& lp) {
    hp = pkbf(a, b);
    lp = pkbf(a - bflo(hp), b - bfhi(hp));
}

#define MMA(d, a0, a1, a2, a3, b0, b1)                                      \
    asm volatile("mma.sync.aligned.m16n8k16.row.col.f32.bf16.bf16.f32 "     \
                 "{%0,%1,%2,%3},{%4,%5,%6,%7},{%8,%9},{%0,%1,%2,%3};"       \
                 : "+f"((d)[0]), "+f"((d)[1]), "+f"((d)[2]), "+f"((d)[3])   \
                 : "r"(a0), "r"(a1), "r"(a2), "r"(a3), "r"(b0), "r"(b1))

// bias + LN + leaky on [16 x 32] block; emit next-stage A frags
__device__ __forceinline__ void ln_block(float acc[4][4],
                                         const float* __restrict__ bias,
                                         const float* __restrict__ gg,
                                         const float* __restrict__ bb,
                                         int t, u32 oh[2][4], u32 ol[2][4])
{
    float s0 = 0.f, q0 = 0.f, s1 = 0.f, q1 = 0.f;
#pragma unroll
    for (int nn = 0; nn < 4; nn++) {
        float2 bv = *(const float2*)(bias + 8 * nn + 2 * t);
        acc[nn][0] += bv.x; acc[nn][1] += bv.y;
        acc[nn][2] += bv.x; acc[nn][3] += bv.y;
        s0 += acc[nn][0] + acc[nn][1];
        q0 += acc[nn][0] * acc[nn][0] + acc[nn][1] * acc[nn][1];
        s1 += acc[nn][2] + acc[nn][3];
        q1 += acc[nn][2] * acc[nn][2] + acc[nn][3] * acc[nn][3];
    }
#pragma unroll
    for (int m = 1; m < 4; m <<= 1) {
        s0 += __shfl_xor_sync(0xffffffffu, s0, m, 4);
        q0 += __shfl_xor_sync(0xffffffffu, q0, m, 4);
        s1 += __shfl_xor_sync(0xffffffffu, s1, m, 4);
        q1 += __shfl_xor_sync(0xffffffffu, q1, m, 4);
    }
    const float c = 1.0f / 32.0f;
    const float m0 = s0 * c, r0 = rsqrtf(fmaf(-m0, m0, q0 * c) + 1e-5f);
    const float m1 = s1 * c, r1 = rsqrtf(fmaf(-m1, m1, q1 * c) + 1e-5f);

    float y[4][4];
#pragma unroll
    for (int nn = 0; nn < 4; nn++) {
        float2 gv = *(const float2*)(gg + 8 * nn + 2 * t);
        float2 bv = *(const float2*)(bb + 8 * nn + 2 * t);
        float u;
        u = fmaf((acc[nn][0] - m0) * r0, gv.x, bv.x); y[nn][0] = fmaxf(u, 0.01f * u);
        u = fmaf((acc[nn][1] - m0) * r0, gv.y, bv.y); y[nn][1] = fmaxf(u, 0.01f * u);
        u = fmaf((acc[nn][2] - m1) * r1, gv.x, bv.x); y[nn][2] = fmaxf(u, 0.01f * u);
        u = fmaf((acc[nn][3] - m1) * r1, gv.y, bv.y); y[nn][3] = fmaxf(u, 0.01f * u);
    }
#pragma unroll
    for (int kk = 0; kk < 2; kk++) {
        split2(y[2 * kk][0],     y[2 * kk][1],     oh[kk][0], ol[kk][0]);
        split2(y[2 * kk][2],     y[2 * kk][3],     oh[kk][1], ol[kk][1]);
        split2(y[2 * kk + 1][0], y[2 * kk + 1][1], oh[kk][2], ol[kk][2]);
        split2(y[2 * kk + 1][2], y[2 * kk + 1][3], oh[kk][3], ol[kk][3]);
    }
}

__device__ __forceinline__ void loadx(const float* __restrict__ x, int tile, int g, int t,
                                      int nrows, float4 xa[4], float4 xb[4])
{
    const int r0 = tile * 16 + g, r1 = r0 + 8;
    const float* b0 = x + (size_t)r0 * 64 + 4 * t;
    const float* b1 = x + (size_t)r1 * 64 + 4 * t;
    const bool v0 = r0 < nrows, v1 = r1 < nrows;
#pragma unroll
    for (int kk = 0; kk < 4; kk++) {
        xa[kk] = v0 ? __ldcs((const float4*)(b0 + 16 * kk)) : make_float4(0.f, 0.f, 0.f, 0.f);
        xb[kk] = v1 ? __ldcs((const float4*)(b1 + 16 * kk)) : make_float4(0.f, 0.f, 0.f, 0.f);
    }
}

// ---------------- single fused kernel: per-CTA fold prologue + R6 body ----------------
__global__ void __launch_bounds__(128, 3)
fused_kernel(const float* __restrict__ x, float* __restrict__ out,
             const float* __restrict__ w1,  const float* __restrict__ b1,
             const float* __restrict__ wv1, const float* __restrict__ bv1,
             const float* __restrict__ g1,
             const float* __restrict__ l1g, const float* __restrict__ l1b,
             const float* __restrict__ w2,  const float* __restrict__ b2,
             const float* __restrict__ wv2, const float* __restrict__ bv2,
             const float* __restrict__ g2,
             const float* __restrict__ l2g, const float* __restrict__ l2b,
             const float* __restrict__ wo,  const float* __restrict__ bo,
             int nrows, int ntiles)
{
    __shared__ uint4 w1s[512];            // GEMM1 frags (8 KB)
    __shared__ uint4 w3s[512];            // GEMM3 frags (8 KB)
    __shared__ float sp[192];             // ab | l1g | l1b | cb | l2g | l2b
    __shared__ float bos[64];
    __shared__ float scr[2048];           // fold scratch: Af (8 KB), then Cf (4 KB)
    const int tid = threadIdx.x;
    const int wid = tid >> 5, lane = tid & 31;
    const int g = lane >> 2, t = lane & 3;
    const float g1v = g1[0], g2v = g2[0];

    // ---- prologue: fold + pack (replaces separate prep launch) ----
    // Af = w1 @ (I + g1*wv1)
    for (int idx = tid; idx < 64 * 32; idx += 128) {
        int i = idx >> 5, j = idx & 31;
        float s = 0.f;
        for (int m = 0; m < 32; m++) s += w1[i * 32 + m] * wv1[m * 32 + j];
        scr[idx] = w1[i * 32 + j] + g1v * s;
    }
    __syncthreads();
    // pack w1 frags (K-permuted for coalesced x loads)
    for (int idx = tid; idx < 512; idx += 128) {
        int kk = idx >> 7, nn = (idx >> 5) & 3, ln = idx & 31;
        int gg = ln >> 2, tt = ln & 3;
        int kb = 16 * kk + 4 * tt, n = 8 * nn + gg;
        float a0 = scr[kb * 32 + n],       a1 = scr[(kb + 1) * 32 + n];
        float a2 = scr[(kb + 2) * 32 + n], a3 = scr[(kb + 3) * 32 + n];
        uint4 v;
        v.x = pkbf(a0, a1); v.y = pkbf(a2, a3);
        v.z = pkbf(a0 - bflo(v.x), a1 - bfhi(v.x));
        v.w = pkbf(a2 - bflo(v.y), a3 - bfhi(v.y));
        w1s[(kk * 4 + nn) * 32 + ln] = v;
    }
    // pack w3 frags from wo (no fold), output-column permuted
    for (int idx = tid; idx < 512; idx += 128) {
        int kk = idx >> 8, nn = (idx >> 5) & 7, ln = idx & 31;
        int gg = ln >> 2, tt = ln & 3;
        int k0 = 16 * kk + 2 * tt;
        int c = 16 * (nn >> 1) + 4 * (gg >> 1) + 2 * (nn & 1) + (gg & 1);
        float a0 = wo[k0 * 64 + c],       a1 = wo[(k0 + 1) * 64 + c];
        float a2 = wo[(k0 + 8) * 64 + c], a3 = wo[(k0 + 9) * 64 + c];
        uint4 v;
        v.x = pkbf(a0, a1); v.y = pkbf(a2, a3);
        v.z = pkbf(a0 - bflo(v.x), a1 - bfhi(v.x));
        v.w = pkbf(a2 - bflo(v.y), a3 - bfhi(v.y));
        w3s[(kk * 8 + nn) * 32 + ln] = v;
    }
    __syncthreads();
    // Cf = w2 @ (I + g2*wv2)
    for (int idx = tid; idx < 32 * 32; idx += 128) {
        int i = idx >> 5, j = idx & 31;
        float s = 0.f;
        for (int m = 0; m < 32; m++) s += w2[i * 32 + m] * wv2[m * 32 + j];
        scr[idx] = w2[i * 32 + j] + g2v * s;
    }
    // folded biases + LN params
    if (tid < 32) {
        int j = tid;
        float s1 = 0.f, s2 = 0.f;
        for (int m = 0; m < 32; m++) {
            s1 += b1[m] * wv1[m * 32 + j];
            s2 += b2[m] * wv2[m * 32 + j];
        }
        sp[j]       = b1[j] + g1v * (s1 + bv1[j]);
        sp[96 + j]  = b2[j] + g2v * (s2 + bv2[j]);
        sp[32 + j]  = l1g[j];
        sp[64 + j]  = l1b[j];
        sp[128 + j] = l2g[j];
        sp[160 + j] = l2b[j];
    }
    if (tid < 64) bos[tid] = bo[tid];
    __syncthreads();

    // GEMM2 weights: each lane packs its own frags straight into registers from Cf
    uint4 w2r[2][4];
#pragma unroll
    for (int kk = 0; kk < 2; kk++)
#pragma unroll
        for (int nn = 0; nn < 4; nn++) {
            int k0 = 16 * kk + 2 * t, n = 8 * nn + g;
            float a0 = scr[k0 * 32 + n],       a1 = scr[(k0 + 1) * 32 + n];
            float a2 = scr[(k0 + 8) * 32 + n], a3 = scr[(k0 + 9) * 32 + n];
            uint4 v;
            v.x = pkbf(a0, a1); v.y = pkbf(a2, a3);
            v.z = pkbf(a0 - bflo(v.x), a1 - bfhi(v.x));
            v.w = pkbf(a2 - bflo(v.y), a3 - bfhi(v.y));
            w2r[kk][nn] = v;
        }
    __syncthreads();

    // ---- main persistent loop (R6 body verbatim) ----
    const int stride = gridDim.x * 4;
    int tile = blockIdx.x * 4 + wid;
    if (tile >= ntiles) return;

    float4 xa[4], xb[4];
    loadx(x, tile, g, t, nrows, xa, xb);

    for (; tile < ntiles; tile += stride) {
        u32 ah[4][4], al[4][4];
#pragma unroll
        for (int kk = 0; kk < 4; kk++) {
            split2(xa[kk].x, xa[kk].y, ah[kk][0], al[kk][0]);
            split2(xb[kk].x, xb[kk].y, ah[kk][1], al[kk][1]);
            split2(xa[kk].z, xa[kk].w, ah[kk][2], al[kk][2]);
            split2(xb[kk].z, xb[kk].w, ah[kk][3], al[kk][3]);
        }
        if (tile + stride < ntiles) loadx(x, tile + stride, g, t, nrows, xa, xb);

        // GEMM1: [16x64]@[64x32]
        float acc[4][4];
#pragma unroll
        for (int nn = 0; nn < 4; nn++) {
            acc[nn][0] = acc[nn][1] = acc[nn][2] = acc[nn][3] = 0.f;
#pragma unroll
            for (int kk = 0; kk < 4; kk++) {
                uint4 w = w1s[(kk * 4 + nn) * 32 + lane];
                MMA(acc[nn], ah[kk][0], ah[kk][1], ah[kk][2], ah[kk][3], w.x, w.y);
                MMA(acc[nn], al[kk][0], al[kk][1], al[kk][2], al[kk][3], w.x, w.y);
                MMA(acc[nn], ah[kk][0], ah[kk][1], ah[kk][2], ah[kk][3], w.z, w.w);
            }
        }

        u32 a2h[2][4], a2l[2][4];
        ln_block(acc, sp + 0, sp + 32, sp + 64, t, a2h, a2l);

        // GEMM2: [16x32]@[32x32], weights in regs
        float acc2[4][4];
#pragma unroll
        for (int nn = 0; nn < 4; nn++) {
            acc2[nn][0] = acc2[nn][1] = acc2[nn][2] = acc2[nn][3] = 0.f;
#pragma unroll
            for (int kk = 0; kk < 2; kk++) {
                uint4 w = w2r[kk][nn];
                MMA(acc2[nn], a2h[kk][0], a2h[kk][1], a2h[kk][2], a2h[kk][3], w.x, w.y);
                MMA(acc2[nn], a2l[kk][0], a2l[kk][1], a2l[kk][2], a2l[kk][3], w.x, w.y);
                MMA(acc2[nn], a2h[kk][0], a2h[kk][1], a2h[kk][2], a2h[kk][3], w.z, w.w);
            }
        }

        u32 a3h[2][4], a3l[2][4];
        ln_block(acc2, sp + 96, sp + 128, sp + 160, t, a3h, a3l);

        // GEMM3: [16x32]@[32x64], store-permuted cols
        float acc3[8][4];
#pragma unroll
        for (int nn = 0; nn < 8; nn++) {
            acc3[nn][0] = acc3[nn][1] = acc3[nn][2] = acc3[nn][3] = 0.f;
#pragma unroll
            for (int kk = 0; kk < 2; kk++) {
                uint4 w = w3s[(kk * 8 + nn) * 32 + lane];
                MMA(acc3[nn], a3h[kk][0], a3h[kk][1], a3h[kk][2], a3h[kk][3], w.x, w.y);
                MMA(acc3[nn], a3l[kk][0], a3l[kk][1], a3l[kk][2], a3l[kk][3], w.x, w.y);
                MMA(acc3[nn], a3h[kk][0], a3h[kk][1], a3h[kk][2], a3h[kk][3], w.z, w.w);
            }
        }

        // + bo, coalesced stores: instr j writes float4 @ logical col 16j+4t
        const int r0 = tile * 16 + g, r1 = r0 + 8;
        float* o0 = out + (size_t)r0 * 64;
        float* o1 = out + (size_t)r1 * 64;
        const bool v0 = r0 < nrows, v1 = r1 < nrows;
#pragma unroll
        for (int j = 0; j < 4; j++) {
            float4 b = *(const float4*)(bos + 16 * j + 4 * t);
            if (v0) {
                float4 v;
                v.x = acc3[2 * j][0]     + b.x;
                v.y = acc3[2 * j][1]     + b.y;
                v.z = acc3[2 * j + 1][0] + b.z;
                v.w = acc3[2 * j + 1][1] + b.w;
                __stcs((float4*)(o0 + 16 * j + 4 * t), v);
            }
            if (v1) {
                float4 v;
                v.x = acc3[2 * j][2]     + b.x;
                v.y = acc3[2 * j][3]     + b.y;
                v.z = acc3[2 * j + 1][2] + b.z;
                v.w = acc3[2 * j + 1][3] + b.w;
                __stcs((float4*)(o1 + 16 * j + 4 * t), v);
            }
        }
    }
}

extern "C" void kernel_launch(void* const* d_in, const int* in_sizes, int n_in,
                              void* d_out, int out_size)
{
    const float* x   = (const float*)d_in[0];
    const float* w1  = (const float*)d_in[1];
    const float* b1  = (const float*)d_in[2];
    const float* wv1 = (const float*)d_in[7];
    const float* bv1 = (const float*)d_in[8];
    const float* g1  = (const float*)d_in[9];
    const float* l1g = (const float*)d_in[10];
    const float* l1b = (const float*)d_in[11];
    const float* w2  = (const float*)d_in[12];
    const float* b2  = (const float*)d_in[13];
    const float* wv2 = (const float*)d_in[18];
    const float* bv2 = (const float*)d_in[19];
    const float* g2  = (const float*)d_in[20];
    const float* l2g = (const float*)d_in[21];
    const float* l2b = (const float*)d_in[22];
    const float* wo  = (const float*)d_in[23];
    const float* bo  = (const float*)d_in[24];

    const int B = in_sizes[0] / 64;
    const int ntiles = (B + 15) / 16;

    int grid = 3 * 148;                       // 3 CTAs/SM x 4 warps, persistent, ONE launch
    int need = (ntiles + 3) / 4;
    if (grid > need) grid = need;
    fused_kernel<<<grid, 128>>>(x, (float*)d_out,
                                w1, b1, wv1, bv1, g1, l1g, l1b,
                                w2, b2, wv2, bv2, g2, l2g, l2b, wo, bo,
                                B, ntiles);
}